// round 1
// baseline (speedup 1.0000x reference)
#include <cuda_runtime.h>
#include <cstdint>

// Problem constants
#define B_     4096
#define D_INN  4096
#define D_PROJ 1024
#define N_CLS  32
#define NC0    32
#define NC1    64

// Output layout: (parent_logits, child0, child1, parent_proj, child_proj) flattened fp32
#define OFF_PLOG 0
#define OFF_C0   (B_ * N_CLS)                 // 131072
#define OFF_C1   (OFF_C0 + B_ * NC0)          // 262144
#define OFF_P    (OFF_C1 + B_ * NC1)          // 524288
#define OFF_S    (OFF_P + B_ * D_PROJ)        // 4718592

// ---------------------------------------------------------------------------
// K1: C[4096, 1024] = A[4096, 4096] @ W[4096, 1024] + bias
// 128x128 block tile, BK=8, 256 threads, 8x8 register tile, double-buffered smem.
// ---------------------------------------------------------------------------
__global__ __launch_bounds__(256, 2)
void sgemm128(const float* __restrict__ A, const float* __restrict__ W,
              const float* __restrict__ bias, float* __restrict__ C)
{
    const int K = D_INN;
    const int N = D_PROJ;

    __shared__ float As[2][8][128];   // transposed A tile: As[k][m]
    __shared__ float Bs[2][8][128];   // Bs[k][n]

    const int tid = threadIdx.x;
    const int bx = blockIdx.x;        // n-tile
    const int by = blockIdx.y;        // m-tile
    const int tx = tid & 15;          // 16 threads over 128 cols (8 each)
    const int ty = tid >> 4;          // 16 threads over 128 rows (8 each)

    // Global load pointers
    // A tile: 128 rows x 8 cols; each thread loads one float4 (row = tid/2, col4 = tid%2)
    const float* Aptr = A + (size_t)(by * 128 + (tid >> 1)) * K + (tid & 1) * 4;
    // W tile: 8 rows x 128 cols; thread loads float4 at (k = tid/32, n = (tid%32)*4)
    const float* Wptr = W + (size_t)(tid >> 5) * N + bx * 128 + (tid & 31) * 4;

    float acc[8][8];
    #pragma unroll
    for (int i = 0; i < 8; i++)
        #pragma unroll
        for (int j = 0; j < 8; j++) acc[i][j] = 0.f;

    // Prologue: load tile 0 into buffer 0
    {
        float4 a = *reinterpret_cast<const float4*>(Aptr);
        float4 b = *reinterpret_cast<const float4*>(Wptr);
        const int kc = (tid & 1) * 4;
        const int mr = tid >> 1;
        As[0][kc + 0][mr] = a.x;
        As[0][kc + 1][mr] = a.y;
        As[0][kc + 2][mr] = a.z;
        As[0][kc + 3][mr] = a.w;
        *reinterpret_cast<float4*>(&Bs[0][tid >> 5][(tid & 31) * 4]) = b;
    }
    __syncthreads();

    int buf = 0;
    const int nt = K / 8;             // 512
    for (int t = 0; t < nt; t++) {
        float4 an, bn;
        const bool has_next = (t + 1 < nt);
        if (has_next) {
            an = *reinterpret_cast<const float4*>(Aptr + (size_t)(t + 1) * 8);
            bn = *reinterpret_cast<const float4*>(Wptr + (size_t)(t + 1) * 8 * N);
        }

        #pragma unroll
        for (int k = 0; k < 8; k++) {
            float ar[8], br[8];
            *reinterpret_cast<float4*>(ar)     = *reinterpret_cast<const float4*>(&As[buf][k][ty * 8]);
            *reinterpret_cast<float4*>(ar + 4) = *reinterpret_cast<const float4*>(&As[buf][k][ty * 8 + 4]);
            *reinterpret_cast<float4*>(br)     = *reinterpret_cast<const float4*>(&Bs[buf][k][tx * 8]);
            *reinterpret_cast<float4*>(br + 4) = *reinterpret_cast<const float4*>(&Bs[buf][k][tx * 8 + 4]);
            #pragma unroll
            for (int i = 0; i < 8; i++)
                #pragma unroll
                for (int j = 0; j < 8; j++)
                    acc[i][j] += ar[i] * br[j];
        }

        if (has_next) {
            const int kc = (tid & 1) * 4;
            const int mr = tid >> 1;
            As[buf ^ 1][kc + 0][mr] = an.x;
            As[buf ^ 1][kc + 1][mr] = an.y;
            As[buf ^ 1][kc + 2][mr] = an.z;
            As[buf ^ 1][kc + 3][mr] = an.w;
            *reinterpret_cast<float4*>(&Bs[buf ^ 1][tid >> 5][(tid & 31) * 4]) = bn;
            buf ^= 1;
        }
        __syncthreads();
    }

    // Epilogue: add bias, store float4
    const int row0 = by * 128 + ty * 8;
    const int col0 = bx * 128 + tx * 8;
    #pragma unroll
    for (int i = 0; i < 8; i++) {
        #pragma unroll
        for (int j = 0; j < 8; j += 4) {
            float4 v;
            v.x = acc[i][j + 0] + bias[col0 + j + 0];
            v.y = acc[i][j + 1] + bias[col0 + j + 1];
            v.z = acc[i][j + 2] + bias[col0 + j + 2];
            v.w = acc[i][j + 3] + bias[col0 + j + 3];
            *reinterpret_cast<float4*>(&C[(size_t)(row0 + i) * N + col0 + j]) = v;
        }
    }
}

// ---------------------------------------------------------------------------
// K2: parent_logits[4096, 32] = P[4096, 1024] @ Wc[1024, 32] + bc
// One thread per output element; warp = one row, lanes = 32 cols.
// P[row,k] is warp-uniform (L1 broadcast); Wc[k*32+col] coalesced, L1-resident.
// ---------------------------------------------------------------------------
__global__ __launch_bounds__(256)
void parent_logits_kernel(const float* __restrict__ P, const float* __restrict__ Wc,
                          const float* __restrict__ bc, float* __restrict__ out)
{
    const int g   = blockIdx.x * blockDim.x + threadIdx.x;   // 0 .. 131071
    const int row = g >> 5;
    const int col = g & 31;
    const float* p = P + (size_t)row * D_PROJ;
    float acc = 0.f;
    #pragma unroll 8
    for (int k = 0; k < D_PROJ; k++)
        acc += p[k] * __ldg(&Wc[k * N_CLS + col]);
    out[OFF_PLOG + g] = acc + bc[col];
}

// ---------------------------------------------------------------------------
// K3: per-sample gathered expert matvecs.
// Block per sample: stage S[b,:] (4 KB) in smem, 4 warps x 24 outputs each;
// each output is one warp-reduced float4 dot over 1024. Weight rows come
// from L2 (cw0+cw1 = 12 MB resident).
// ---------------------------------------------------------------------------
__global__ __launch_bounds__(128)
void child_kernel(const float* __restrict__ S, const int* __restrict__ y,
                  const float* __restrict__ cw0, const float* __restrict__ cb0,
                  const float* __restrict__ cw1, const float* __restrict__ cb1,
                  float* __restrict__ out)
{
    __shared__ float4 s4[D_PROJ / 4];   // 256 float4 = 4 KB

    const int b    = blockIdx.x;
    const int tid  = threadIdx.x;
    const int lane = tid & 31;
    const int warp = tid >> 5;

    const float4* Sg = reinterpret_cast<const float4*>(S + (size_t)b * D_PROJ);
    s4[tid]       = Sg[tid];
    s4[tid + 128] = Sg[tid + 128];
    __syncthreads();

    const int c = y[b];

    for (int o = warp; o < NC0 + NC1; o += 4) {
        const float* Wr;
        float bia;
        if (o < NC0) {
            Wr  = cw0 + ((size_t)c * NC0 + o) * D_PROJ;
            bia = cb0[c * NC0 + o];
        } else {
            const int o1 = o - NC0;
            Wr  = cw1 + ((size_t)c * NC1 + o1) * D_PROJ;
            bia = cb1[c * NC1 + o1];
        }
        const float4* W4 = reinterpret_cast<const float4*>(Wr);
        float acc = 0.f;
        #pragma unroll
        for (int it = 0; it < 8; it++) {
            const int k = lane + it * 32;
            float4 w = __ldg(&W4[k]);
            float4 s = s4[k];
            acc += w.x * s.x + w.y * s.y + w.z * s.z + w.w * s.w;
        }
        #pragma unroll
        for (int off = 16; off; off >>= 1)
            acc += __shfl_down_sync(0xffffffffu, acc, off);
        if (lane == 0) {
            if (o < NC0) out[OFF_C0 + b * NC0 + o] = acc + bia;
            else         out[OFF_C1 + b * NC1 + (o - NC0)] = acc + bia;
        }
    }
}

// ---------------------------------------------------------------------------
// Launch
// ---------------------------------------------------------------------------
extern "C" void kernel_launch(void* const* d_in, const int* in_sizes, int n_in,
                              void* d_out, int out_size)
{
    const float* x   = (const float*)d_in[0];
    const int*   y   = (const int*)  d_in[1];
    const float* Wp  = (const float*)d_in[2];
    const float* bp  = (const float*)d_in[3];
    const float* Ws  = (const float*)d_in[4];
    const float* bs  = (const float*)d_in[5];
    const float* Wc  = (const float*)d_in[6];
    const float* bc  = (const float*)d_in[7];
    const float* cw0 = (const float*)d_in[8];
    const float* cb0 = (const float*)d_in[9];
    const float* cw1 = (const float*)d_in[10];
    const float* cb1 = (const float*)d_in[11];
    float* out = (float*)d_out;

    dim3 grid(D_PROJ / 128, B_ / 128);   // (8, 32)

    // P = x @ Wp + bp ; S = x @ Ws + bs
    sgemm128<<<grid, 256>>>(x, Wp, bp, out + OFF_P);
    sgemm128<<<grid, 256>>>(x, Ws, bs, out + OFF_S);

    // parent_logits = P @ Wc + bc
    parent_logits_kernel<<<(B_ * N_CLS) / 256, 256>>>(out + OFF_P, Wc, bc, out);

    // child logits via per-sample expert gather
    child_kernel<<<B_, 128>>>(out + OFF_S, y, cw0, cb0, cw1, cb1, out);
}

// round 2
// speedup vs baseline: 2.0493x; 2.0493x over previous
#include <cuda_runtime.h>
#include <cstdint>

// Problem constants
#define B_     4096
#define D_INN  4096
#define D_PROJ 1024
#define N_CLS  32
#define NC0    32
#define NC1    64

// Output layout: (parent_logits, child0, child1, parent_proj, child_proj) flattened fp32
#define OFF_PLOG 0
#define OFF_C0   (B_ * N_CLS)                 // 131072
#define OFF_C1   (OFF_C0 + B_ * NC0)          // 262144
#define OFF_P    (OFF_C1 + B_ * NC1)          // 524288
#define OFF_S    (OFF_P + B_ * D_PROJ)        // 4718592

// ---------------------------------------------------------------------------
// K1: tf32 tensor-core GEMM. C[4096,1024] = A[4096,4096] @ W[4096,1024] + bias
// BM=128, BN=128, BK=16; 256 threads = 8 warps (4 m x 2 n); warp tile 32x64.
// mma.sync.aligned.m16n8k8.row.col.f32.tf32.tf32.f32
// fp32 -> tf32 via cvt.rna at the smem-store stage (zero-mean rounding).
// ---------------------------------------------------------------------------
#define BM 128
#define BN 128
#define BK 16
#define PAD 4

__device__ __forceinline__ uint32_t f2tf32(float x) {
    uint32_t r;
    asm("cvt.rna.tf32.f32 %0, %1;" : "=r"(r) : "f"(x));
    return r;
}

__device__ __forceinline__ void mma_tf32(float* d, const uint32_t* a, const uint32_t* b) {
    asm volatile(
        "mma.sync.aligned.m16n8k8.row.col.f32.tf32.tf32.f32 "
        "{%0,%1,%2,%3}, {%4,%5,%6,%7}, {%8,%9}, {%0,%1,%2,%3};"
        : "+f"(d[0]), "+f"(d[1]), "+f"(d[2]), "+f"(d[3])
        : "r"(a[0]), "r"(a[1]), "r"(a[2]), "r"(a[3]), "r"(b[0]), "r"(b[1]));
}

__global__ __launch_bounds__(256)
void tf32_gemm(const float* __restrict__ A, const float* __restrict__ W,
               const float* __restrict__ bias, float* __restrict__ C)
{
    // smem tiles hold tf32-converted bit patterns (as uint32)
    __shared__ uint32_t As[2][BK][BM + PAD];
    __shared__ uint32_t Bs[2][BK][BN + PAD];

    const int tid  = threadIdx.x;
    const int warp = tid >> 5;
    const int lane = tid & 31;
    const int wm   = warp >> 1;        // 0..3  (m quadrant, 32 rows each)
    const int wn   = warp & 1;         // 0..1  (n half, 64 cols each)
    const int gid  = lane >> 2;        // 0..7
    const int tig  = lane & 3;         // 0..3

    const int mblk = blockIdx.y * BM;
    const int nblk = blockIdx.x * BN;

    // A tile load map: thread t -> rows (t/4, t/4+64), col4 = (t%4)*4
    const int a_row  = tid >> 2;             // 0..63
    const int a_col4 = (tid & 3) * 4;        // 0,4,8,12
    const float* Ag = A + (size_t)(mblk + a_row) * D_INN + a_col4;

    // B tile load map: f = tid + i*256 -> k = f/32 (0..15), n4 = (f%32)*4
    const int b_k = tid >> 5;                // 0..7 (second half: +8)
    const int b_n = (tid & 31) * 4;
    const float* Bg = W + (size_t)b_k * D_PROJ + nblk + b_n;

    float acc[2][8][4];
    #pragma unroll
    for (int mt = 0; mt < 2; mt++)
        #pragma unroll
        for (int nt = 0; nt < 8; nt++)
            #pragma unroll
            for (int i = 0; i < 4; i++) acc[mt][nt][i] = 0.f;

    float4 ar0, ar1, br0, br1;

    // ---- prologue: load tile 0 into regs, convert+store to buf 0 ----
    ar0 = *reinterpret_cast<const float4*>(Ag);
    ar1 = *reinterpret_cast<const float4*>(Ag + 64 * D_INN);
    br0 = *reinterpret_cast<const float4*>(Bg);
    br1 = *reinterpret_cast<const float4*>(Bg + 8 * D_PROJ);
    {
        As[0][a_col4 + 0][a_row] = f2tf32(ar0.x);
        As[0][a_col4 + 1][a_row] = f2tf32(ar0.y);
        As[0][a_col4 + 2][a_row] = f2tf32(ar0.z);
        As[0][a_col4 + 3][a_row] = f2tf32(ar0.w);
        As[0][a_col4 + 0][a_row + 64] = f2tf32(ar1.x);
        As[0][a_col4 + 1][a_row + 64] = f2tf32(ar1.y);
        As[0][a_col4 + 2][a_row + 64] = f2tf32(ar1.z);
        As[0][a_col4 + 3][a_row + 64] = f2tf32(ar1.w);
        uint4 v0 = { f2tf32(br0.x), f2tf32(br0.y), f2tf32(br0.z), f2tf32(br0.w) };
        uint4 v1 = { f2tf32(br1.x), f2tf32(br1.y), f2tf32(br1.z), f2tf32(br1.w) };
        *reinterpret_cast<uint4*>(&Bs[0][b_k][b_n])     = v0;
        *reinterpret_cast<uint4*>(&Bs[0][b_k + 8][b_n]) = v1;
    }
    __syncthreads();

    const int nk = D_INN / BK;   // 256
    int buf = 0;

    for (int t = 0; t < nk; t++) {
        const bool has_next = (t + 1 < nk);
        if (has_next) {
            const float* Agn = Ag + (size_t)(t + 1) * BK;
            const float* Bgn = Bg + (size_t)(t + 1) * BK * D_PROJ;
            ar0 = *reinterpret_cast<const float4*>(Agn);
            ar1 = *reinterpret_cast<const float4*>(Agn + 64 * D_INN);
            br0 = *reinterpret_cast<const float4*>(Bgn);
            br1 = *reinterpret_cast<const float4*>(Bgn + 8 * D_PROJ);
        }

        // ---- compute on buf ----
        #pragma unroll
        for (int ks = 0; ks < 2; ks++) {
            const int kb = ks * 8;
            uint32_t afr[2][4], bfr[8][2];
            #pragma unroll
            for (int mt = 0; mt < 2; mt++) {
                const int m = wm * 32 + mt * 16;
                afr[mt][0] = As[buf][kb + tig][m + gid];
                afr[mt][1] = As[buf][kb + tig][m + gid + 8];
                afr[mt][2] = As[buf][kb + tig + 4][m + gid];
                afr[mt][3] = As[buf][kb + tig + 4][m + gid + 8];
            }
            #pragma unroll
            for (int nt = 0; nt < 8; nt++) {
                const int n = wn * 64 + nt * 8;
                bfr[nt][0] = Bs[buf][kb + tig][n + gid];
                bfr[nt][1] = Bs[buf][kb + tig + 4][n + gid];
            }
            #pragma unroll
            for (int mt = 0; mt < 2; mt++)
                #pragma unroll
                for (int nt = 0; nt < 8; nt++)
                    mma_tf32(acc[mt][nt], afr[mt], bfr[nt]);
        }

        // ---- stage next tile into other buffer ----
        if (has_next) {
            const int nb = buf ^ 1;
            As[nb][a_col4 + 0][a_row] = f2tf32(ar0.x);
            As[nb][a_col4 + 1][a_row] = f2tf32(ar0.y);
            As[nb][a_col4 + 2][a_row] = f2tf32(ar0.z);
            As[nb][a_col4 + 3][a_row] = f2tf32(ar0.w);
            As[nb][a_col4 + 0][a_row + 64] = f2tf32(ar1.x);
            As[nb][a_col4 + 1][a_row + 64] = f2tf32(ar1.y);
            As[nb][a_col4 + 2][a_row + 64] = f2tf32(ar1.z);
            As[nb][a_col4 + 3][a_row + 64] = f2tf32(ar1.w);
            uint4 v0 = { f2tf32(br0.x), f2tf32(br0.y), f2tf32(br0.z), f2tf32(br0.w) };
            uint4 v1 = { f2tf32(br1.x), f2tf32(br1.y), f2tf32(br1.z), f2tf32(br1.w) };
            *reinterpret_cast<uint4*>(&Bs[nb][b_k][b_n])     = v0;
            *reinterpret_cast<uint4*>(&Bs[nb][b_k + 8][b_n]) = v1;
        }
        __syncthreads();
        buf ^= 1;
    }

    // ---- epilogue: add bias, store float2 pairs ----
    // c0,c1 -> (row=gid, col=2*tig,2*tig+1); c2,c3 -> (row=gid+8, same cols)
    #pragma unroll
    for (int mt = 0; mt < 2; mt++) {
        const int row = mblk + wm * 32 + mt * 16 + gid;
        #pragma unroll
        for (int nt = 0; nt < 8; nt++) {
            const int col = nblk + wn * 64 + nt * 8 + 2 * tig;
            const float b0 = bias[col], b1 = bias[col + 1];
            float2 v0 = { acc[mt][nt][0] + b0, acc[mt][nt][1] + b1 };
            float2 v1 = { acc[mt][nt][2] + b0, acc[mt][nt][3] + b1 };
            *reinterpret_cast<float2*>(&C[(size_t)row * D_PROJ + col])       = v0;
            *reinterpret_cast<float2*>(&C[(size_t)(row + 8) * D_PROJ + col]) = v1;
        }
    }
}

// ---------------------------------------------------------------------------
// K2: parent_logits[4096, 32] = P[4096, 1024] @ Wc[1024, 32] + bc
// ---------------------------------------------------------------------------
__global__ __launch_bounds__(256)
void parent_logits_kernel(const float* __restrict__ P, const float* __restrict__ Wc,
                          const float* __restrict__ bc, float* __restrict__ out)
{
    const int g   = blockIdx.x * blockDim.x + threadIdx.x;   // 0 .. 131071
    const int row = g >> 5;
    const int col = g & 31;
    const float* p = P + (size_t)row * D_PROJ;
    float acc = 0.f;
    #pragma unroll 8
    for (int k = 0; k < D_PROJ; k++)
        acc += p[k] * __ldg(&Wc[k * N_CLS + col]);
    out[OFF_PLOG + g] = acc + bc[col];
}

// ---------------------------------------------------------------------------
// K3: per-sample gathered expert matvecs (unchanged from R1).
// ---------------------------------------------------------------------------
__global__ __launch_bounds__(128)
void child_kernel(const float* __restrict__ S, const int* __restrict__ y,
                  const float* __restrict__ cw0, const float* __restrict__ cb0,
                  const float* __restrict__ cw1, const float* __restrict__ cb1,
                  float* __restrict__ out)
{
    __shared__ float4 s4[D_PROJ / 4];   // 256 float4 = 4 KB

    const int b    = blockIdx.x;
    const int tid  = threadIdx.x;
    const int lane = tid & 31;
    const int warp = tid >> 5;

    const float4* Sg = reinterpret_cast<const float4*>(S + (size_t)b * D_PROJ);
    s4[tid]       = Sg[tid];
    s4[tid + 128] = Sg[tid + 128];
    __syncthreads();

    const int c = y[b];

    for (int o = warp; o < NC0 + NC1; o += 4) {
        const float* Wr;
        float bia;
        if (o < NC0) {
            Wr  = cw0 + ((size_t)c * NC0 + o) * D_PROJ;
            bia = cb0[c * NC0 + o];
        } else {
            const int o1 = o - NC0;
            Wr  = cw1 + ((size_t)c * NC1 + o1) * D_PROJ;
            bia = cb1[c * NC1 + o1];
        }
        const float4* W4 = reinterpret_cast<const float4*>(Wr);
        float acc = 0.f;
        #pragma unroll
        for (int it = 0; it < 8; it++) {
            const int k = lane + it * 32;
            float4 w = __ldg(&W4[k]);
            float4 s = s4[k];
            acc += w.x * s.x + w.y * s.y + w.z * s.z + w.w * s.w;
        }
        #pragma unroll
        for (int off = 16; off; off >>= 1)
            acc += __shfl_down_sync(0xffffffffu, acc, off);
        if (lane == 0) {
            if (o < NC0) out[OFF_C0 + b * NC0 + o] = acc + bia;
            else         out[OFF_C1 + b * NC1 + (o - NC0)] = acc + bia;
        }
    }
}

// ---------------------------------------------------------------------------
// Launch
// ---------------------------------------------------------------------------
extern "C" void kernel_launch(void* const* d_in, const int* in_sizes, int n_in,
                              void* d_out, int out_size)
{
    const float* x   = (const float*)d_in[0];
    const int*   y   = (const int*)  d_in[1];
    const float* Wp  = (const float*)d_in[2];
    const float* bp  = (const float*)d_in[3];
    const float* Ws  = (const float*)d_in[4];
    const float* bs  = (const float*)d_in[5];
    const float* Wc  = (const float*)d_in[6];
    const float* bc  = (const float*)d_in[7];
    const float* cw0 = (const float*)d_in[8];
    const float* cb0 = (const float*)d_in[9];
    const float* cw1 = (const float*)d_in[10];
    const float* cb1 = (const float*)d_in[11];
    float* out = (float*)d_out;

    dim3 grid(D_PROJ / BN, B_ / BM);   // (8, 32)

    // P = x @ Wp + bp ; S = x @ Ws + bs   (tf32 tensor cores)
    tf32_gemm<<<grid, 256>>>(x, Wp, bp, out + OFF_P);
    tf32_gemm<<<grid, 256>>>(x, Ws, bs, out + OFF_S);

    // parent_logits = P @ Wc + bc
    parent_logits_kernel<<<(B_ * N_CLS) / 256, 256>>>(out + OFF_P, Wc, bc, out);

    // child logits via per-sample expert gather
    child_kernel<<<B_, 128>>>(out + OFF_S, y, cw0, cb0, cw1, cb1, out);
}

// round 4
// speedup vs baseline: 3.4152x; 1.6665x over previous
#include <cuda_runtime.h>
#include <cuda_fp16.h>
#include <cstdint>

// Problem constants
#define B_     4096
#define D_INN  4096
#define D_PROJ 1024
#define N_CLS  32
#define NC0    32
#define NC1    64

// Output layout: (parent_logits, child0, child1, parent_proj, child_proj) flattened fp32
#define OFF_PLOG 0
#define OFF_C0   (B_ * N_CLS)                 // 131072
#define OFF_C1   (OFF_C0 + B_ * NC0)          // 262144
#define OFF_P    (OFF_C1 + B_ * NC1)          // 524288
#define OFF_S    (OFF_P + B_ * D_PROJ)        // 4718592

#define WSCALE 4096.0f
#define OSCALE (1.0f / 4096.0f)

// ===========================================================================
// helpers
// ===========================================================================
__device__ __forceinline__ uint32_t smem_u32(const void* p) {
    uint32_t a;
    asm("{ .reg .u64 t; cvta.to.shared.u64 t, %1; cvt.u32.u64 %0, t; }" : "=r"(a) : "l"(p));
    return a;
}

// pack two fp32 -> fp16x2 (lo = second operand)
__device__ __forceinline__ uint32_t f2h2(float hi, float lo) {
    uint32_t r;
    asm("cvt.rn.f16x2.f32 %0, %1, %2;" : "=r"(r) : "f"(hi), "f"(lo));
    return r;
}

__device__ __forceinline__ void ldsm_x4(uint32_t* r, uint32_t addr) {
    asm volatile("ldmatrix.sync.aligned.m8n8.x4.shared.b16 {%0,%1,%2,%3}, [%4];"
                 : "=r"(r[0]), "=r"(r[1]), "=r"(r[2]), "=r"(r[3]) : "r"(addr));
}
__device__ __forceinline__ void ldsm_x4_t(uint32_t* r, uint32_t addr) {
    asm volatile("ldmatrix.sync.aligned.m8n8.x4.trans.shared.b16 {%0,%1,%2,%3}, [%4];"
                 : "=r"(r[0]), "=r"(r[1]), "=r"(r[2]), "=r"(r[3]) : "r"(addr));
}

__device__ __forceinline__ void mma_f16(float* d, const uint32_t* a, const uint32_t* b) {
    asm volatile(
        "mma.sync.aligned.m16n8k16.row.col.f32.f16.f16.f32 "
        "{%0,%1,%2,%3}, {%4,%5,%6,%7}, {%8,%9}, {%0,%1,%2,%3};"
        : "+f"(d[0]), "+f"(d[1]), "+f"(d[2]), "+f"(d[3])
        : "r"(a[0]), "r"(a[1]), "r"(a[2]), "r"(a[3]), "r"(b[0]), "r"(b[1]));
}

// ===========================================================================
// K1: fp16-TC GEMM. C[4096,1024] = A[4096,4096] @ W[4096,1024] + bias
// BM=128, BN=128, BK=32. 256 threads = 8 warps (4m x 2n), warp tile 32x64.
// A -> fp16 direct; W scaled by 2^12 -> fp16 (avoids subnormals); acc scaled
// back by 2^-12 in epilogue. ldmatrix(+trans) operand fetch, double-buffered.
// ===========================================================================
#define AP 40     // As pitch in halves (80 B rows: 20-word stride, bank-clean ldmatrix)
#define BP 136    // Bs pitch in halves (272 B rows)
#define AS_BUF_BYTES (128 * AP * 2)   // 10240
#define BS_BUF_BYTES (32 * BP * 2)    // 8704

__global__ __launch_bounds__(256, 2)
void hgemm(const float* __restrict__ A, const float* __restrict__ W,
           const float* __restrict__ bias, float* __restrict__ C)
{
    __shared__ __align__(16) __half As[2][128][AP];
    __shared__ __align__(16) __half Bs[2][32][BP];

    const int tid  = threadIdx.x;
    const int warp = tid >> 5;
    const int lane = tid & 31;
    const int wm   = warp >> 1;      // 0..3
    const int wn   = warp & 1;       // 0..1
    const int mblk = blockIdx.y * 128;
    const int nblk = blockIdx.x * 128;

    const uint32_t as0 = smem_u32(&As[0][0][0]);
    const uint32_t bs0 = smem_u32(&Bs[0][0][0]);

    // global load maps
    const int a_r = tid >> 3;             // base row (passes add +32)
    const int a_q = (tid & 7) * 4;        // col (floats)
    const int b_k = tid >> 3;             // k row 0..31
    const int b_n = (tid & 7) * 16;       // n base (floats), 4x float4

    // ldmatrix lane offsets
    const int lm_row = (lane & 7) + ((lane >> 3) & 1) * 8;
    const int lm_hi  = (lane >> 4) * 8;
    const uint32_t a_lane_off = (uint32_t)(lm_row * AP + lm_hi) * 2;
    const uint32_t b_lane_off = (uint32_t)(lm_row * BP + lm_hi) * 2;

    float acc[2][8][4];
    #pragma unroll
    for (int mt = 0; mt < 2; mt++)
        #pragma unroll
        for (int nt = 0; nt < 8; nt++)
            #pragma unroll
            for (int i = 0; i < 4; i++) acc[mt][nt][i] = 0.f;

    float4 av[4], bv[4];

    // ---- prologue: tile 0 -> buf 0 ----
    #pragma unroll
    for (int p = 0; p < 4; p++)
        av[p] = *reinterpret_cast<const float4*>(A + (size_t)(mblk + a_r + p * 32) * D_INN + a_q);
    #pragma unroll
    for (int q = 0; q < 4; q++)
        bv[q] = *reinterpret_cast<const float4*>(W + (size_t)b_k * D_PROJ + nblk + b_n + q * 4);
    #pragma unroll
    for (int p = 0; p < 4; p++) {
        const uint32_t addr = as0 + (uint32_t)((a_r + p * 32) * AP + a_q) * 2;
        asm volatile("st.shared.v2.b32 [%0], {%1,%2};"
                     :: "r"(addr), "r"(f2h2(av[p].y, av[p].x)), "r"(f2h2(av[p].w, av[p].z)) : "memory");
    }
    #pragma unroll
    for (int q = 0; q < 4; q++) {
        const uint32_t addr = bs0 + (uint32_t)(b_k * BP + b_n + q * 4) * 2;
        asm volatile("st.shared.v2.b32 [%0], {%1,%2};"
                     :: "r"(addr),
                        "r"(f2h2(bv[q].y * WSCALE, bv[q].x * WSCALE)),
                        "r"(f2h2(bv[q].w * WSCALE, bv[q].z * WSCALE)) : "memory");
    }
    __syncthreads();

    const int NT = D_INN / 32;   // 128 k-tiles

    for (int t = 0; t < NT; t++) {
        const int buf = t & 1;
        const uint32_t asb = as0 + buf * AS_BUF_BYTES;
        const uint32_t bsb = bs0 + buf * BS_BUF_BYTES;
        const uint32_t asn = as0 + (buf ^ 1) * AS_BUF_BYTES;
        const uint32_t bsn = bs0 + (buf ^ 1) * BS_BUF_BYTES;
        const bool hn = (t + 1 < NT);

        // stage next A loads (latency hidden by ks=0 compute)
        if (hn) {
            #pragma unroll
            for (int p = 0; p < 4; p++)
                av[p] = *reinterpret_cast<const float4*>(
                    A + (size_t)(mblk + a_r + p * 32) * D_INN + (t + 1) * 32 + a_q);
        }

        // ---- compute ks = 0 ----
        {
            const int kb = 0;
            uint32_t afr[2][4], bfr[8][2];
            #pragma unroll
            for (int mt = 0; mt < 2; mt++)
                ldsm_x4(afr[mt], asb + a_lane_off +
                        (uint32_t)((wm * 32 + mt * 16) * AP + kb) * 2);
            #pragma unroll
            for (int nb = 0; nb < 4; nb++) {
                uint32_t r[4];
                ldsm_x4_t(r, bsb + b_lane_off +
                          (uint32_t)(kb * BP + wn * 64 + nb * 16) * 2);
                bfr[2 * nb][0] = r[0]; bfr[2 * nb][1] = r[1];
                bfr[2 * nb + 1][0] = r[2]; bfr[2 * nb + 1][1] = r[3];
            }
            #pragma unroll
            for (int mt = 0; mt < 2; mt++)
                #pragma unroll
                for (int nt = 0; nt < 8; nt++)
                    mma_f16(acc[mt][nt], afr[mt], bfr[nt]);
        }

        // store staged A -> next buf; stage next B loads (hidden by ks=1)
        if (hn) {
            #pragma unroll
            for (int p = 0; p < 4; p++) {
                const uint32_t addr = asn + (uint32_t)((a_r + p * 32) * AP + a_q) * 2;
                asm volatile("st.shared.v2.b32 [%0], {%1,%2};"
                             :: "r"(addr), "r"(f2h2(av[p].y, av[p].x)), "r"(f2h2(av[p].w, av[p].z)) : "memory");
            }
            #pragma unroll
            for (int q = 0; q < 4; q++)
                bv[q] = *reinterpret_cast<const float4*>(
                    W + (size_t)((t + 1) * 32 + b_k) * D_PROJ + nblk + b_n + q * 4);
        }

        // ---- compute ks = 1 ----
        {
            const int kb = 16;
            uint32_t afr[2][4], bfr[8][2];
            #pragma unroll
            for (int mt = 0; mt < 2; mt++)
                ldsm_x4(afr[mt], asb + a_lane_off +
                        (uint32_t)((wm * 32 + mt * 16) * AP + kb) * 2);
            #pragma unroll
            for (int nb = 0; nb < 4; nb++) {
                uint32_t r[4];
                ldsm_x4_t(r, bsb + b_lane_off +
                          (uint32_t)(kb * BP + wn * 64 + nb * 16) * 2);
                bfr[2 * nb][0] = r[0]; bfr[2 * nb][1] = r[1];
                bfr[2 * nb + 1][0] = r[2]; bfr[2 * nb + 1][1] = r[3];
            }
            #pragma unroll
            for (int mt = 0; mt < 2; mt++)
                #pragma unroll
                for (int nt = 0; nt < 8; nt++)
                    mma_f16(acc[mt][nt], afr[mt], bfr[nt]);
        }

        if (hn) {
            #pragma unroll
            for (int q = 0; q < 4; q++) {
                const uint32_t addr = bsn + (uint32_t)(b_k * BP + b_n + q * 4) * 2;
                asm volatile("st.shared.v2.b32 [%0], {%1,%2};"
                             :: "r"(addr),
                                "r"(f2h2(bv[q].y * WSCALE, bv[q].x * WSCALE)),
                                "r"(f2h2(bv[q].w * WSCALE, bv[q].z * WSCALE)) : "memory");
            }
        }
        __syncthreads();
    }

    // ---- epilogue: unscale, add bias, store ----
    const int gid = lane >> 2;
    const int tig = lane & 3;
    #pragma unroll
    for (int mt = 0; mt < 2; mt++) {
        const int row = mblk + wm * 32 + mt * 16 + gid;
        #pragma unroll
        for (int nt = 0; nt < 8; nt++) {
            const int col = nblk + wn * 64 + nt * 8 + 2 * tig;
            const float b0 = bias[col], b1 = bias[col + 1];
            float2 v0 = { acc[mt][nt][0] * OSCALE + b0, acc[mt][nt][1] * OSCALE + b1 };
            float2 v1 = { acc[mt][nt][2] * OSCALE + b0, acc[mt][nt][3] * OSCALE + b1 };
            *reinterpret_cast<float2*>(&C[(size_t)row * D_PROJ + col])       = v0;
            *reinterpret_cast<float2*>(&C[(size_t)(row + 8) * D_PROJ + col]) = v1;
        }
    }
}

// ===========================================================================
// K2: parent_logits[4096, 32] = P[4096, 1024] @ Wc[1024, 32] + bc
// ===========================================================================
__global__ __launch_bounds__(256)
void parent_logits_kernel(const float* __restrict__ P, const float* __restrict__ Wc,
                          const float* __restrict__ bc, float* __restrict__ out)
{
    const int g   = blockIdx.x * blockDim.x + threadIdx.x;
    const int row = g >> 5;
    const int col = g & 31;
    const float* p = P + (size_t)row * D_PROJ;
    float acc = 0.f;
    #pragma unroll 8
    for (int k = 0; k < D_PROJ; k++)
        acc += p[k] * __ldg(&Wc[k * N_CLS + col]);
    out[OFF_PLOG + g] = acc + bc[col];
}

// ===========================================================================
// K3: class-bucketed expert logits.
// Bucket samples by label, then per (class, 32-sample chunk) block compute
// [<=32 x 1024] @ [1024 x 96] with smem-staged S rows and weight rows.
// Weight traffic drops from 1.5 GB (per-sample gather) to ~2x12 MB.
// ===========================================================================
__device__ int g_cnt[N_CLS];
__device__ int g_idx[N_CLS][B_];

__global__ void zero_cnt_kernel() {
    if (threadIdx.x < N_CLS) g_cnt[threadIdx.x] = 0;
}

__global__ __launch_bounds__(256)
void bucket_kernel(const int* __restrict__ y) {
    const int b = blockIdx.x * blockDim.x + threadIdx.x;
    const int c = y[b];
    const int p = atomicAdd(&g_cnt[c], 1);
    g_idx[c][p] = b;
}

#define CH_NS 32
__global__ __launch_bounds__(256)
void child_gemm(const float* __restrict__ S,
                const float* __restrict__ cw0, const float* __restrict__ cb0,
                const float* __restrict__ cw1, const float* __restrict__ cb1,
                float* __restrict__ out)
{
    __shared__ float Ss[CH_NS][68];
    __shared__ float Ws[96][68];
    __shared__ int   sidx[CH_NS];

    const int c    = blockIdx.x;
    const int cnt  = g_cnt[c];
    const int base = blockIdx.y * CH_NS;
    if (base >= cnt) return;
    const int ns = min(CH_NS, cnt - base);

    const int tid = threadIdx.x;
    const int tx  = tid & 15;   // 6 outputs: tx + 16*oi
    const int ty  = tid >> 4;   // 2 samples: ty + 16*i

    if (tid < CH_NS)
        sidx[tid] = g_idx[c][base + min(tid, ns - 1)];   // clamp -> safe loads
    __syncthreads();

    float acc[2][6];
    #pragma unroll
    for (int i = 0; i < 2; i++)
        #pragma unroll
        for (int o = 0; o < 6; o++) acc[i][o] = 0.f;

    const float* w0 = cw0 + (size_t)c * NC0 * D_PROJ;
    const float* w1 = cw1 + (size_t)c * NC1 * D_PROJ;

    for (int kb = 0; kb < D_PROJ; kb += 64) {
        __syncthreads();
        // stage S rows: 32 x 16 float4, 2 per thread
        #pragma unroll
        for (int j = 0; j < 2; j++) {
            const int f = tid + j * 256;
            const int s = f >> 4, q = (f & 15) * 4;
            *reinterpret_cast<float4*>(&Ss[s][q]) =
                *reinterpret_cast<const float4*>(S + (size_t)sidx[s] * D_PROJ + kb + q);
        }
        // stage W rows: 96 x 16 float4, 6 per thread
        #pragma unroll
        for (int j = 0; j < 6; j++) {
            const int f = tid + j * 256;
            const int o = f >> 4, q = (f & 15) * 4;
            const float* wp = (o < NC0) ? (w0 + (size_t)o * D_PROJ)
                                        : (w1 + (size_t)(o - NC0) * D_PROJ);
            *reinterpret_cast<float4*>(&Ws[o][q]) =
                *reinterpret_cast<const float4*>(wp + kb + q);
        }
        __syncthreads();

        #pragma unroll
        for (int kk = 0; kk < 64; kk += 4) {
            float4 sv[2], wv[6];
            sv[0] = *reinterpret_cast<const float4*>(&Ss[ty][kk]);
            sv[1] = *reinterpret_cast<const float4*>(&Ss[ty + 16][kk]);
            #pragma unroll
            for (int o = 0; o < 6; o++)
                wv[o] = *reinterpret_cast<const float4*>(&Ws[tx + 16 * o][kk]);
            #pragma unroll
            for (int i = 0; i < 2; i++)
                #pragma unroll
                for (int o = 0; o < 6; o++)
                    acc[i][o] += sv[i].x * wv[o].x + sv[i].y * wv[o].y
                               + sv[i].z * wv[o].z + sv[i].w * wv[o].w;
        }
    }

    #pragma unroll
    for (int i = 0; i < 2; i++) {
        const int s = ty + 16 * i;
        if (s < ns) {
            const int g = sidx[s];
            #pragma unroll
            for (int oi = 0; oi < 6; oi++) {
                const int o = tx + 16 * oi;
                if (o < NC0)
                    out[OFF_C0 + g * NC0 + o] = acc[i][oi] + cb0[c * NC0 + o];
                else
                    out[OFF_C1 + g * NC1 + (o - NC0)] = acc[i][oi] + cb1[c * NC1 + (o - NC0)];
            }
        }
    }
}

// ===========================================================================
// Launch
// ===========================================================================
extern "C" void kernel_launch(void* const* d_in, const int* in_sizes, int n_in,
                              void* d_out, int out_size)
{
    const float* x   = (const float*)d_in[0];
    const int*   y   = (const int*)  d_in[1];
    const float* Wp  = (const float*)d_in[2];
    const float* bp  = (const float*)d_in[3];
    const float* Ws  = (const float*)d_in[4];
    const float* bs  = (const float*)d_in[5];
    const float* Wc  = (const float*)d_in[6];
    const float* bc  = (const float*)d_in[7];
    const float* cw0 = (const float*)d_in[8];
    const float* cb0 = (const float*)d_in[9];
    const float* cw1 = (const float*)d_in[10];
    const float* cb1 = (const float*)d_in[11];
    float* out = (float*)d_out;

    // bucket samples by class (used by child_gemm at the end)
    zero_cnt_kernel<<<1, 32>>>();
    bucket_kernel<<<B_ / 256, 256>>>(y);

    dim3 grid(D_PROJ / 128, B_ / 128);   // (8, 32) = 256 CTAs, one wave @ 2 CTA/SM

    hgemm<<<grid, 256>>>(x, Wp, bp, out + OFF_P);
    hgemm<<<grid, 256>>>(x, Ws, bs, out + OFF_S);

    parent_logits_kernel<<<(B_ * N_CLS) / 256, 256>>>(out + OFF_P, Wc, bc, out);

    child_gemm<<<dim3(N_CLS, B_ / CH_NS), 256>>>(out + OFF_S, cw0, cb0, cw1, cb1, out);
}

// round 5
// speedup vs baseline: 5.3125x; 1.5555x over previous
#include <cuda_runtime.h>
#include <cuda_fp16.h>
#include <cstdint>

// Problem constants
#define B_     4096
#define D_INN  4096
#define D_PROJ 1024
#define N_CLS  32
#define NC0    32
#define NC1    64

// Output layout: (parent_logits, child0, child1, parent_proj, child_proj) flattened fp32
#define OFF_PLOG 0
#define OFF_C0   (B_ * N_CLS)                 // 131072
#define OFF_C1   (OFF_C0 + B_ * NC0)          // 262144
#define OFF_P    (OFF_C1 + B_ * NC1)          // 524288
#define OFF_S    (OFF_P + B_ * D_PROJ)        // 4718592

#define WSCALE 4096.0f
#define OSCALE (1.0f / 4096.0f)

// fp16 scratch (static device globals: allocation-free)
__device__ __align__(16) __half g_xh[B_ * D_INN];        // 32 MB
__device__ __align__(16) __half g_wph[D_INN * D_PROJ];   // 8 MB (scaled by WSCALE)
__device__ __align__(16) __half g_wsh[D_INN * D_PROJ];   // 8 MB (scaled by WSCALE)

// ===========================================================================
// helpers
// ===========================================================================
__device__ __forceinline__ uint32_t smem_u32(const void* p) {
    uint32_t a;
    asm("{ .reg .u64 t; cvta.to.shared.u64 t, %1; cvt.u32.u64 %0, t; }" : "=r"(a) : "l"(p));
    return a;
}

__device__ __forceinline__ uint32_t f2h2(float hi, float lo) {
    uint32_t r;
    asm("cvt.rn.f16x2.f32 %0, %1, %2;" : "=r"(r) : "f"(hi), "f"(lo));
    return r;
}

__device__ __forceinline__ void ldsm_x4(uint32_t* r, uint32_t addr) {
    asm volatile("ldmatrix.sync.aligned.m8n8.x4.shared.b16 {%0,%1,%2,%3}, [%4];"
                 : "=r"(r[0]), "=r"(r[1]), "=r"(r[2]), "=r"(r[3]) : "r"(addr));
}
__device__ __forceinline__ void ldsm_x4_t(uint32_t* r, uint32_t addr) {
    asm volatile("ldmatrix.sync.aligned.m8n8.x4.trans.shared.b16 {%0,%1,%2,%3}, [%4];"
                 : "=r"(r[0]), "=r"(r[1]), "=r"(r[2]), "=r"(r[3]) : "r"(addr));
}

__device__ __forceinline__ void mma_f16(float* d, const uint32_t* a, const uint32_t* b) {
    asm volatile(
        "mma.sync.aligned.m16n8k16.row.col.f32.f16.f16.f32 "
        "{%0,%1,%2,%3}, {%4,%5,%6,%7}, {%8,%9}, {%0,%1,%2,%3};"
        : "+f"(d[0]), "+f"(d[1]), "+f"(d[2]), "+f"(d[3])
        : "r"(a[0]), "r"(a[1]), "r"(a[2]), "r"(a[3]), "r"(b[0]), "r"(b[1]));
}

#define CP_ASYNC16(saddr, gaddr) \
    asm volatile("cp.async.cg.shared.global [%0], [%1], 16;" :: "r"(saddr), "l"(gaddr))
#define CP_COMMIT() asm volatile("cp.async.commit_group;" ::: "memory")
#define CP_WAIT1()  asm volatile("cp.async.wait_group 1;"  ::: "memory")

// ===========================================================================
// K0: fp32 -> fp16 pre-conversion (x, Wp*WSCALE, Ws*WSCALE)
// ===========================================================================
#define NXF4 (B_ * D_INN / 4)      // 4M float4
#define NWF4 (D_INN * D_PROJ / 4)  // 1M float4 each

__global__ __launch_bounds__(256)
void convert_kernel(const float* __restrict__ x,
                    const float* __restrict__ Wp, const float* __restrict__ Ws)
{
    const int i = blockIdx.x * blockDim.x + threadIdx.x;
    if (i < NXF4) {
        float4 v = *reinterpret_cast<const float4*>(x + i * 4);
        uint2 h = { f2h2(v.y, v.x), f2h2(v.w, v.z) };
        *reinterpret_cast<uint2*>(&g_xh[i * 4]) = h;
    } else if (i < NXF4 + NWF4) {
        const int j = i - NXF4;
        float4 v = *reinterpret_cast<const float4*>(Wp + j * 4);
        uint2 h = { f2h2(v.y * WSCALE, v.x * WSCALE), f2h2(v.w * WSCALE, v.z * WSCALE) };
        *reinterpret_cast<uint2*>(&g_wph[j * 4]) = h;
    } else {
        const int j = i - NXF4 - NWF4;
        float4 v = *reinterpret_cast<const float4*>(Ws + j * 4);
        uint2 h = { f2h2(v.y * WSCALE, v.x * WSCALE), f2h2(v.w * WSCALE, v.z * WSCALE) };
        *reinterpret_cast<uint2*>(&g_wsh[j * 4]) = h;
    }
}

// ===========================================================================
// K1: fp16 TC GEMM with cp.async 3-stage pipeline.
// C[4096,1024] = A_h[4096,4096] @ W_h[4096,1024] * OSCALE + bias
// BM=BN=128, BK=64 halves. 128 threads = 4 warps (2m x 2n), warp tile 64x64.
// A smem: 128 rows x 128B, swizzle chunk^= row&7. B smem: 64 rows x 256B,
// swizzle chunk^= row&7 (within 128B phase). All ldsm + cp.async conflict-free.
// ===========================================================================
#define STAGES 3
#define BKH    64
#define A_ST_BYTES (128 * 128)               // 16384
#define B_ST_BYTES (64 * 256)                // 16384
#define ST_BYTES   (A_ST_BYTES + B_ST_BYTES) // 32768
#define SMEM_GEMM  (STAGES * ST_BYTES)       // 98304

__global__ __launch_bounds__(128, 2)
void hgemm2(int which, const float* __restrict__ bias, float* __restrict__ C)
{
    extern __shared__ char sm[];
    const uint32_t sb = smem_u32(sm);

    const __half* __restrict__ Ah = g_xh;
    const __half* __restrict__ Wh = which ? g_wsh : g_wph;

    const int tid  = threadIdx.x;
    const int warp = tid >> 5;
    const int lane = tid & 31;
    const int wm   = warp >> 1;   // 0..1
    const int wn   = warp & 1;    // 0..1
    const int mblk = blockIdx.y * 128;
    const int nblk = blockIdx.x * 128;

    // ldmatrix lane geometry (validated mapping from R4)
    const int lm_row = (lane & 7) + ((lane >> 3) & 1) * 8;  // 0..15
    const int hi     = lane >> 4;                           // 0..1
    const int rm     = lm_row & 7;

    float acc[4][8][4];
    #pragma unroll
    for (int mt = 0; mt < 4; mt++)
        #pragma unroll
        for (int nt = 0; nt < 8; nt++)
            #pragma unroll
            for (int i = 0; i < 4; i++) acc[mt][nt][i] = 0.f;

    // ---- cp.async stage issue ----
    auto issue = [&](int slot, int t) {
        const uint32_t abase = sb + slot * ST_BYTES;
        const uint32_t bbase = abase + A_ST_BYTES;
        #pragma unroll
        for (int j = 0; j < 8; j++) {              // A: 1024 chunks of 16B
            const int id  = tid + 128 * j;
            const int row = id >> 3, c = id & 7;
            const __half* g = Ah + (size_t)(mblk + row) * D_INN + t * BKH + c * 8;
            CP_ASYNC16(abase + row * 128 + ((c ^ (row & 7)) << 4), g);
        }
        #pragma unroll
        for (int j = 0; j < 8; j++) {              // B: 1024 chunks of 16B
            const int id = tid + 128 * j;
            const int k  = id >> 4, c = id & 15;
            const __half* g = Wh + (size_t)(t * BKH + k) * D_PROJ + nblk + c * 8;
            CP_ASYNC16(bbase + k * 256 + ((c ^ (k & 7)) << 4), g);
        }
    };

    // prologue: stages 0,1
    issue(0, 0); CP_COMMIT();
    issue(1, 1); CP_COMMIT();

    const int NT = D_INN / BKH;   // 64
    for (int t = 0; t < NT; t++) {
        CP_WAIT1();
        __syncthreads();
        if (t + 2 < NT) {
            int slot = t + 2; slot = (slot >= STAGES) ? (slot % STAGES) : slot;
            issue(slot, t + 2);
        }
        CP_COMMIT();   // commit every iter (possibly empty) to keep group count uniform

        const int cs = t % STAGES;
        const uint32_t abase = sb + cs * ST_BYTES;
        const uint32_t bbase = abase + A_ST_BYTES;

        #pragma unroll
        for (int s = 0; s < 4; s++) {             // 4 k16 steps per stage
            uint32_t afr[4][4], bfr[8][2];
            #pragma unroll
            for (int mt = 0; mt < 4; mt++) {
                const int row0 = wm * 64 + mt * 16 + lm_row;
                ldsm_x4(afr[mt], abase + (uint32_t)(row0 * 128)
                                       + ((uint32_t)((2 * s + hi) ^ rm) << 4));
            }
            #pragma unroll
            for (int nb = 0; nb < 4; nb++) {
                uint32_t r[4];
                const int krow = 16 * s + lm_row;
                ldsm_x4_t(r, bbase + (uint32_t)(krow * 256)
                                   + ((uint32_t)((wn * 8 + nb * 2 + hi) ^ rm) << 4));
                bfr[2 * nb][0] = r[0]; bfr[2 * nb][1] = r[1];
                bfr[2 * nb + 1][0] = r[2]; bfr[2 * nb + 1][1] = r[3];
            }
            #pragma unroll
            for (int mt = 0; mt < 4; mt++)
                #pragma unroll
                for (int nt = 0; nt < 8; nt++)
                    mma_f16(acc[mt][nt], afr[mt], bfr[nt]);
        }
    }

    // ---- epilogue: unscale, add bias, store ----
    const int gid = lane >> 2;
    const int tig = lane & 3;
    #pragma unroll
    for (int mt = 0; mt < 4; mt++) {
        const int row = mblk + wm * 64 + mt * 16 + gid;
        #pragma unroll
        for (int nt = 0; nt < 8; nt++) {
            const int col = nblk + wn * 64 + nt * 8 + 2 * tig;
            const float b0 = bias[col], b1 = bias[col + 1];
            float2 v0 = { acc[mt][nt][0] * OSCALE + b0, acc[mt][nt][1] * OSCALE + b1 };
            float2 v1 = { acc[mt][nt][2] * OSCALE + b0, acc[mt][nt][3] * OSCALE + b1 };
            *reinterpret_cast<float2*>(&C[(size_t)row * D_PROJ + col])       = v0;
            *reinterpret_cast<float2*>(&C[(size_t)(row + 8) * D_PROJ + col]) = v1;
        }
    }
}

// ===========================================================================
// K2: parent_logits[4096, 32] = P[4096, 1024] @ Wc[1024, 32] + bc (vectorized)
// ===========================================================================
__global__ __launch_bounds__(256)
void parent_logits_kernel(const float* __restrict__ P, const float* __restrict__ Wc,
                          const float* __restrict__ bc, float* __restrict__ out)
{
    const int g   = blockIdx.x * blockDim.x + threadIdx.x;
    const int row = g >> 5;
    const int col = g & 31;
    const float4* p4 = reinterpret_cast<const float4*>(P + (size_t)row * D_PROJ);
    float acc = 0.f;
    #pragma unroll 8
    for (int k4 = 0; k4 < D_PROJ / 4; k4++) {
        float4 v = __ldg(&p4[k4]);
        const float* wr = Wc + k4 * 4 * N_CLS + col;
        acc += v.x * __ldg(wr) + v.y * __ldg(wr + 32)
             + v.z * __ldg(wr + 64) + v.w * __ldg(wr + 96);
    }
    out[OFF_PLOG + g] = acc + bc[col];
}

// ===========================================================================
// K3: class-bucketed expert logits (unchanged from R4).
// ===========================================================================
__device__ int g_cnt[N_CLS];
__device__ int g_idx[N_CLS][B_];

__global__ void zero_cnt_kernel() {
    if (threadIdx.x < N_CLS) g_cnt[threadIdx.x] = 0;
}

__global__ __launch_bounds__(256)
void bucket_kernel(const int* __restrict__ y) {
    const int b = blockIdx.x * blockDim.x + threadIdx.x;
    const int c = y[b];
    const int p = atomicAdd(&g_cnt[c], 1);
    g_idx[c][p] = b;
}

#define CH_NS 32
__global__ __launch_bounds__(256)
void child_gemm(const float* __restrict__ S,
                const float* __restrict__ cw0, const float* __restrict__ cb0,
                const float* __restrict__ cw1, const float* __restrict__ cb1,
                float* __restrict__ out)
{
    __shared__ float Ss[CH_NS][68];
    __shared__ float Ws[96][68];
    __shared__ int   sidx[CH_NS];

    const int c    = blockIdx.x;
    const int cnt  = g_cnt[c];
    const int base = blockIdx.y * CH_NS;
    if (base >= cnt) return;
    const int ns = min(CH_NS, cnt - base);

    const int tid = threadIdx.x;
    const int tx  = tid & 15;
    const int ty  = tid >> 4;

    if (tid < CH_NS)
        sidx[tid] = g_idx[c][base + min(tid, ns - 1)];
    __syncthreads();

    float acc[2][6];
    #pragma unroll
    for (int i = 0; i < 2; i++)
        #pragma unroll
        for (int o = 0; o < 6; o++) acc[i][o] = 0.f;

    const float* w0 = cw0 + (size_t)c * NC0 * D_PROJ;
    const float* w1 = cw1 + (size_t)c * NC1 * D_PROJ;

    for (int kb = 0; kb < D_PROJ; kb += 64) {
        __syncthreads();
        #pragma unroll
        for (int j = 0; j < 2; j++) {
            const int f = tid + j * 256;
            const int s = f >> 4, q = (f & 15) * 4;
            *reinterpret_cast<float4*>(&Ss[s][q]) =
                *reinterpret_cast<const float4*>(S + (size_t)sidx[s] * D_PROJ + kb + q);
        }
        #pragma unroll
        for (int j = 0; j < 6; j++) {
            const int f = tid + j * 256;
            const int o = f >> 4, q = (f & 15) * 4;
            const float* wp = (o < NC0) ? (w0 + (size_t)o * D_PROJ)
                                        : (w1 + (size_t)(o - NC0) * D_PROJ);
            *reinterpret_cast<float4*>(&Ws[o][q]) =
                *reinterpret_cast<const float4*>(wp + kb + q);
        }
        __syncthreads();

        #pragma unroll
        for (int kk = 0; kk < 64; kk += 4) {
            float4 sv[2], wv[6];
            sv[0] = *reinterpret_cast<const float4*>(&Ss[ty][kk]);
            sv[1] = *reinterpret_cast<const float4*>(&Ss[ty + 16][kk]);
            #pragma unroll
            for (int o = 0; o < 6; o++)
                wv[o] = *reinterpret_cast<const float4*>(&Ws[tx + 16 * o][kk]);
            #pragma unroll
            for (int i = 0; i < 2; i++)
                #pragma unroll
                for (int o = 0; o < 6; o++)
                    acc[i][o] += sv[i].x * wv[o].x + sv[i].y * wv[o].y
                               + sv[i].z * wv[o].z + sv[i].w * wv[o].w;
        }
    }

    #pragma unroll
    for (int i = 0; i < 2; i++) {
        const int s = ty + 16 * i;
        if (s < ns) {
            const int g = sidx[s];
            #pragma unroll
            for (int oi = 0; oi < 6; oi++) {
                const int o = tx + 16 * oi;
                if (o < NC0)
                    out[OFF_C0 + g * NC0 + o] = acc[i][oi] + cb0[c * NC0 + o];
                else
                    out[OFF_C1 + g * NC1 + (o - NC0)] = acc[i][oi] + cb1[c * NC1 + (o - NC0)];
            }
        }
    }
}

// ===========================================================================
// Launch
// ===========================================================================
extern "C" void kernel_launch(void* const* d_in, const int* in_sizes, int n_in,
                              void* d_out, int out_size)
{
    const float* x   = (const float*)d_in[0];
    const int*   y   = (const int*)  d_in[1];
    const float* Wp  = (const float*)d_in[2];
    const float* bp  = (const float*)d_in[3];
    const float* Ws  = (const float*)d_in[4];
    const float* bs  = (const float*)d_in[5];
    const float* Wc  = (const float*)d_in[6];
    const float* bc  = (const float*)d_in[7];
    const float* cw0 = (const float*)d_in[8];
    const float* cb0 = (const float*)d_in[9];
    const float* cw1 = (const float*)d_in[10];
    const float* cb1 = (const float*)d_in[11];
    float* out = (float*)d_out;

    static bool attr_set = false;
    if (!attr_set) {
        cudaFuncSetAttribute(hgemm2, cudaFuncAttributeMaxDynamicSharedMemorySize, SMEM_GEMM);
        attr_set = true;
    }

    // fp16 pre-conversion of x, Wp, Ws
    convert_kernel<<<(NXF4 + 2 * NWF4 + 255) / 256, 256>>>(x, Wp, Ws);

    // bucket samples by class
    zero_cnt_kernel<<<1, 32>>>();
    bucket_kernel<<<B_ / 256, 256>>>(y);

    dim3 grid(D_PROJ / 128, B_ / 128);   // (8, 32) = 256 CTAs

    hgemm2<<<grid, 128, SMEM_GEMM>>>(0, bp, out + OFF_P);
    hgemm2<<<grid, 128, SMEM_GEMM>>>(1, bs, out + OFF_S);

    parent_logits_kernel<<<(B_ * N_CLS) / 256, 256>>>(out + OFF_P, Wc, bc, out);

    child_gemm<<<dim3(N_CLS, B_ / CH_NS), 256>>>(out + OFF_S, cw0, cb0, cw1, cb1, out);
}

// round 7
// speedup vs baseline: 5.4937x; 1.0341x over previous
#include <cuda_runtime.h>
#include <cuda_fp16.h>
#include <cstdint>

// Problem constants
#define B_     4096
#define D_INN  4096
#define D_PROJ 1024
#define N_CLS  32
#define NC0    32
#define NC1    64

// Output layout: (parent_logits, child0, child1, parent_proj, child_proj) flattened fp32
#define OFF_PLOG 0
#define OFF_C0   (B_ * N_CLS)                 // 131072
#define OFF_C1   (OFF_C0 + B_ * NC0)          // 262144
#define OFF_P    (OFF_C1 + B_ * NC1)          // 524288
#define OFF_S    (OFF_P + B_ * D_PROJ)        // 4718592

#define WSCALE 4096.0f
#define OSCALE (1.0f / 4096.0f)

// fp16 scratch + bucket state (static device globals: allocation-free)
__device__ __align__(16) __half g_xh[B_ * D_INN];        // 32 MB
__device__ __align__(16) __half g_wph[D_INN * D_PROJ];   // 8 MB (scaled by WSCALE)
__device__ __align__(16) __half g_wsh[D_INN * D_PROJ];   // 8 MB (scaled by WSCALE)
__device__ int g_cnt[N_CLS];
__device__ int g_idx[N_CLS][B_];

// ===========================================================================
// helpers
// ===========================================================================
__device__ __forceinline__ uint32_t smem_u32(const void* p) {
    uint32_t a;
    asm("{ .reg .u64 t; cvta.to.shared.u64 t, %1; cvt.u32.u64 %0, t; }" : "=r"(a) : "l"(p));
    return a;
}

__device__ __forceinline__ uint32_t f2h2(float hi, float lo) {
    uint32_t r;
    asm("cvt.rn.f16x2.f32 %0, %1, %2;" : "=r"(r) : "f"(hi), "f"(lo));
    return r;
}

__device__ __forceinline__ void ldsm_x4(uint32_t* r, uint32_t addr) {
    asm volatile("ldmatrix.sync.aligned.m8n8.x4.shared.b16 {%0,%1,%2,%3}, [%4];"
                 : "=r"(r[0]), "=r"(r[1]), "=r"(r[2]), "=r"(r[3]) : "r"(addr));
}
__device__ __forceinline__ void ldsm_x4_t(uint32_t* r, uint32_t addr) {
    asm volatile("ldmatrix.sync.aligned.m8n8.x4.trans.shared.b16 {%0,%1,%2,%3}, [%4];"
                 : "=r"(r[0]), "=r"(r[1]), "=r"(r[2]), "=r"(r[3]) : "r"(addr));
}

__device__ __forceinline__ void mma_f16(float* d, const uint32_t* a, const uint32_t* b) {
    asm volatile(
        "mma.sync.aligned.m16n8k16.row.col.f32.f16.f16.f32 "
        "{%0,%1,%2,%3}, {%4,%5,%6,%7}, {%8,%9}, {%0,%1,%2,%3};"
        : "+f"(d[0]), "+f"(d[1]), "+f"(d[2]), "+f"(d[3])
        : "r"(a[0]), "r"(a[1]), "r"(a[2]), "r"(a[3]), "r"(b[0]), "r"(b[1]));
}

#define CP_ASYNC16(saddr, gaddr) \
    asm volatile("cp.async.cg.shared.global [%0], [%1], 16;" :: "r"(saddr), "l"(gaddr))
#define CP_COMMIT() asm volatile("cp.async.commit_group;" ::: "memory")
#define CP_WAIT1()  asm volatile("cp.async.wait_group 1;"  ::: "memory")

// ===========================================================================
// K0: fp32 -> fp16 pre-conversion (x, Wp*WSCALE, Ws*WSCALE) + g_cnt zeroing
// ===========================================================================
#define NXF4 (B_ * D_INN / 4)      // 4M float4
#define NWF4 (D_INN * D_PROJ / 4)  // 1M float4 each

__global__ __launch_bounds__(256)
void convert_kernel(const float* __restrict__ x,
                    const float* __restrict__ Wp, const float* __restrict__ Ws)
{
    if (blockIdx.x == 0 && threadIdx.x < N_CLS) g_cnt[threadIdx.x] = 0;

    const int i = blockIdx.x * blockDim.x + threadIdx.x;
    if (i < NXF4) {
        float4 v = *reinterpret_cast<const float4*>(x + i * 4);
        uint2 h = { f2h2(v.y, v.x), f2h2(v.w, v.z) };
        *reinterpret_cast<uint2*>(&g_xh[i * 4]) = h;
    } else if (i < NXF4 + NWF4) {
        const int j = i - NXF4;
        float4 v = *reinterpret_cast<const float4*>(Wp + j * 4);
        uint2 h = { f2h2(v.y * WSCALE, v.x * WSCALE), f2h2(v.w * WSCALE, v.z * WSCALE) };
        *reinterpret_cast<uint2*>(&g_wph[j * 4]) = h;
    } else {
        const int j = i - NXF4 - NWF4;
        float4 v = *reinterpret_cast<const float4*>(Ws + j * 4);
        uint2 h = { f2h2(v.y * WSCALE, v.x * WSCALE), f2h2(v.w * WSCALE, v.z * WSCALE) };
        *reinterpret_cast<uint2*>(&g_wsh[j * 4]) = h;
    }
}

// ===========================================================================
// K1: fp16 TC GEMM, both projections in one launch (blockIdx.z selects),
// bucket pass embedded as the z==2 plane.
// C = A_h @ W_h * OSCALE + bias.  BM=BN=128, BK=64 halves, 4 warps (2x2),
// warp tile 64x64, cp.async 3-stage pipeline, fragment double-buffering.
// ===========================================================================
#define STAGES 3
#define BKH    64
#define A_ST_BYTES (128 * 128)               // 16384
#define B_ST_BYTES (64 * 256)                // 16384
#define ST_BYTES   (A_ST_BYTES + B_ST_BYTES) // 32768
#define SMEM_GEMM  (STAGES * ST_BYTES)       // 98304

__global__ __launch_bounds__(128, 2)
void hgemm2(const int* __restrict__ y,
            const float* __restrict__ bp, const float* __restrict__ bs,
            float* __restrict__ out)
{
    const int z = blockIdx.z;
    if (z == 2) {
        // bucket plane: 32 working blocks x 128 threads = 4096 samples
        const int flat = blockIdx.x + 8 * blockIdx.y;
        if (flat < 32) {
            const int b = flat * 128 + threadIdx.x;
            const int c = y[b];
            const int p = atomicAdd(&g_cnt[c], 1);
            g_idx[c][p] = b;
        }
        return;
    }

    extern __shared__ char sm[];
    const uint32_t sb = smem_u32(sm);

    const __half* __restrict__ Ah = g_xh;
    const __half* __restrict__ Wh = z ? g_wsh : g_wph;
    const float*  __restrict__ bias = z ? bs : bp;
    float* __restrict__ C = out + (z ? OFF_S : OFF_P);

    const int tid  = threadIdx.x;
    const int warp = tid >> 5;
    const int lane = tid & 31;
    const int wm   = warp >> 1;   // 0..1
    const int wn   = warp & 1;    // 0..1
    const int mblk = blockIdx.y * 128;
    const int nblk = blockIdx.x * 128;

    const int lm_row = (lane & 7) + ((lane >> 3) & 1) * 8;  // 0..15
    const int hi     = lane >> 4;                           // 0..1
    const int rm     = lm_row & 7;

    float acc[4][8][4];
    #pragma unroll
    for (int mt = 0; mt < 4; mt++)
        #pragma unroll
        for (int nt = 0; nt < 8; nt++)
            #pragma unroll
            for (int i = 0; i < 4; i++) acc[mt][nt][i] = 0.f;

    auto issue = [&](int slot, int t) {
        const uint32_t abase = sb + slot * ST_BYTES;
        const uint32_t bbase = abase + A_ST_BYTES;
        #pragma unroll
        for (int j = 0; j < 8; j++) {
            const int id  = tid + 128 * j;
            const int row = id >> 3, c = id & 7;
            const __half* g = Ah + (size_t)(mblk + row) * D_INN + t * BKH + c * 8;
            CP_ASYNC16(abase + row * 128 + ((c ^ (row & 7)) << 4), g);
        }
        #pragma unroll
        for (int j = 0; j < 8; j++) {
            const int id = tid + 128 * j;
            const int k  = id >> 4, c = id & 15;
            const __half* g = Wh + (size_t)(t * BKH + k) * D_PROJ + nblk + c * 8;
            CP_ASYNC16(bbase + k * 256 + ((c ^ (k & 7)) << 4), g);
        }
    };

    issue(0, 0); CP_COMMIT();
    issue(1, 1); CP_COMMIT();

    uint32_t afr[2][4][4], bfr[2][8][2];

    // ring cursors (replace modular arithmetic: the R6 crash was a bad wrap)
    int cs = 0;        // stage being computed this iteration
    int ns_slot = 2;   // stage the prefetch writes this iteration

    const int NT = D_INN / BKH;   // 64
    for (int t = 0; t < NT; t++) {
        CP_WAIT1();
        __syncthreads();

        const uint32_t abase = sb + cs * ST_BYTES;
        const uint32_t bbase = abase + A_ST_BYTES;

        auto load_frags = [&](int s, uint32_t (&af)[4][4], uint32_t (&bf)[8][2]) {
            #pragma unroll
            for (int mt = 0; mt < 4; mt++) {
                const int row0 = wm * 64 + mt * 16 + lm_row;
                ldsm_x4(af[mt], abase + (uint32_t)(row0 * 128)
                                      + ((uint32_t)((2 * s + hi) ^ rm) << 4));
            }
            #pragma unroll
            for (int nb = 0; nb < 4; nb++) {
                uint32_t r[4];
                const int krow = 16 * s + lm_row;
                ldsm_x4_t(r, bbase + (uint32_t)(krow * 256)
                                   + ((uint32_t)((wn * 8 + nb * 2 + hi) ^ rm) << 4));
                bf[2 * nb][0] = r[0]; bf[2 * nb][1] = r[1];
                bf[2 * nb + 1][0] = r[2]; bf[2 * nb + 1][1] = r[3];
            }
        };

        // frags for step 0 first: MMAs start before the cp.async burst
        load_frags(0, afr[0], bfr[0]);

        if (t + 2 < NT)
            issue(ns_slot, t + 2);
        CP_COMMIT();   // uniform group accounting (possibly empty)

        #pragma unroll
        for (int s = 0; s < 4; s++) {
            if (s < 3)
                load_frags(s + 1, afr[(s + 1) & 1], bfr[(s + 1) & 1]);
            const int cur = s & 1;
            #pragma unroll
            for (int mt = 0; mt < 4; mt++)
                #pragma unroll
                for (int nt = 0; nt < 8; nt++)
                    mma_f16(acc[mt][nt], afr[cur][mt], bfr[cur][nt]);
        }

        cs      = (cs == STAGES - 1)      ? 0 : cs + 1;
        ns_slot = (ns_slot == STAGES - 1) ? 0 : ns_slot + 1;
    }

    // ---- epilogue: unscale, add bias, store ----
    const int gid = lane >> 2;
    const int tig = lane & 3;
    #pragma unroll
    for (int mt = 0; mt < 4; mt++) {
        const int row = mblk + wm * 64 + mt * 16 + gid;
        #pragma unroll
        for (int nt = 0; nt < 8; nt++) {
            const int col = nblk + wn * 64 + nt * 8 + 2 * tig;
            const float b0 = bias[col], b1 = bias[col + 1];
            float2 v0 = { acc[mt][nt][0] * OSCALE + b0, acc[mt][nt][1] * OSCALE + b1 };
            float2 v1 = { acc[mt][nt][2] * OSCALE + b0, acc[mt][nt][3] * OSCALE + b1 };
            *reinterpret_cast<float2*>(&C[(size_t)row * D_PROJ + col])       = v0;
            *reinterpret_cast<float2*>(&C[(size_t)(row + 8) * D_PROJ + col]) = v1;
        }
    }
}

// ===========================================================================
// K2: fused tail. Blocks [0,512): parent logits. Blocks [512,4608): child
// expert logits (class-bucketed, chunk-major so idle blocks exit together).
// ===========================================================================
#define CH_NS 32
#define PLOG_BLOCKS 512
#define CHILD_BLOCKS (N_CLS * (B_ / CH_NS))   // 4096

__global__ __launch_bounds__(256)
void tail_kernel(const float* __restrict__ Wc, const float* __restrict__ bc,
                 const float* __restrict__ cw0, const float* __restrict__ cb0,
                 const float* __restrict__ cw1, const float* __restrict__ cb1,
                 float* __restrict__ out)
{
    __shared__ float Ss[CH_NS][68];
    __shared__ float Ws[96][68];
    __shared__ int   sidx[CH_NS];

    const int tid = threadIdx.x;

    if (blockIdx.x < PLOG_BLOCKS) {
        // ---- parent logits: P @ Wc + bc ----
        const float* P = out + OFF_P;
        const int g   = blockIdx.x * 256 + tid;
        const int row = g >> 5;
        const int col = g & 31;
        const float4* p4 = reinterpret_cast<const float4*>(P + (size_t)row * D_PROJ);
        float acc = 0.f;
        #pragma unroll 8
        for (int k4 = 0; k4 < D_PROJ / 4; k4++) {
            float4 v = __ldg(&p4[k4]);
            const float* wr = Wc + k4 * 4 * N_CLS + col;
            acc += v.x * __ldg(wr) + v.y * __ldg(wr + 32)
                 + v.z * __ldg(wr + 64) + v.w * __ldg(wr + 96);
        }
        out[OFF_PLOG + g] = acc + bc[col];
        return;
    }

    // ---- child expert logits ----
    const int cb    = blockIdx.x - PLOG_BLOCKS;
    const int c     = cb & (N_CLS - 1);       // class
    const int chunk = cb >> 5;                // 0..127
    const int cnt   = g_cnt[c];
    const int base  = chunk * CH_NS;
    if (base >= cnt) return;
    const int ns = min(CH_NS, cnt - base);

    const float* S = out + OFF_S;
    const int tx = tid & 15;
    const int ty = tid >> 4;

    if (tid < CH_NS)
        sidx[tid] = g_idx[c][base + min(tid, ns - 1)];
    __syncthreads();

    float acc[2][6];
    #pragma unroll
    for (int i = 0; i < 2; i++)
        #pragma unroll
        for (int o = 0; o < 6; o++) acc[i][o] = 0.f;

    const float* w0 = cw0 + (size_t)c * NC0 * D_PROJ;
    const float* w1 = cw1 + (size_t)c * NC1 * D_PROJ;

    for (int kb = 0; kb < D_PROJ; kb += 64) {
        __syncthreads();
        #pragma unroll
        for (int j = 0; j < 2; j++) {
            const int f = tid + j * 256;
            const int s = f >> 4, q = (f & 15) * 4;
            *reinterpret_cast<float4*>(&Ss[s][q]) =
                *reinterpret_cast<const float4*>(S + (size_t)sidx[s] * D_PROJ + kb + q);
        }
        #pragma unroll
        for (int j = 0; j < 6; j++) {
            const int f = tid + j * 256;
            const int o = f >> 4, q = (f & 15) * 4;
            const float* wp = (o < NC0) ? (w0 + (size_t)o * D_PROJ)
                                        : (w1 + (size_t)(o - NC0) * D_PROJ);
            *reinterpret_cast<float4*>(&Ws[o][q]) =
                *reinterpret_cast<const float4*>(wp + kb + q);
        }
        __syncthreads();

        #pragma unroll
        for (int kk = 0; kk < 64; kk += 4) {
            float4 sv[2], wv[6];
            sv[0] = *reinterpret_cast<const float4*>(&Ss[ty][kk]);
            sv[1] = *reinterpret_cast<const float4*>(&Ss[ty + 16][kk]);
            #pragma unroll
            for (int o = 0; o < 6; o++)
                wv[o] = *reinterpret_cast<const float4*>(&Ws[tx + 16 * o][kk]);
            #pragma unroll
            for (int i = 0; i < 2; i++)
                #pragma unroll
                for (int o = 0; o < 6; o++)
                    acc[i][o] += sv[i].x * wv[o].x + sv[i].y * wv[o].y
                               + sv[i].z * wv[o].z + sv[i].w * wv[o].w;
        }
    }

    #pragma unroll
    for (int i = 0; i < 2; i++) {
        const int s = ty + 16 * i;
        if (s < ns) {
            const int g = sidx[s];
            #pragma unroll
            for (int oi = 0; oi < 6; oi++) {
                const int o = tx + 16 * oi;
                if (o < NC0)
                    out[OFF_C0 + g * NC0 + o] = acc[i][oi] + cb0[c * NC0 + o];
                else
                    out[OFF_C1 + g * NC1 + (o - NC0)] = acc[i][oi] + cb1[c * NC1 + (o - NC0)];
            }
        }
    }
}

// ===========================================================================
// Launch: 3 kernels total
// ===========================================================================
extern "C" void kernel_launch(void* const* d_in, const int* in_sizes, int n_in,
                              void* d_out, int out_size)
{
    const float* x   = (const float*)d_in[0];
    const int*   y   = (const int*)  d_in[1];
    const float* Wp  = (const float*)d_in[2];
    const float* bp  = (const float*)d_in[3];
    const float* Ws  = (const float*)d_in[4];
    const float* bs  = (const float*)d_in[5];
    const float* Wc  = (const float*)d_in[6];
    const float* bc  = (const float*)d_in[7];
    const float* cw0 = (const float*)d_in[8];
    const float* cb0 = (const float*)d_in[9];
    const float* cw1 = (const float*)d_in[10];
    const float* cb1 = (const float*)d_in[11];
    float* out = (float*)d_out;

    static bool attr_set = false;
    if (!attr_set) {
        cudaFuncSetAttribute(hgemm2, cudaFuncAttributeMaxDynamicSharedMemorySize, SMEM_GEMM);
        attr_set = true;
    }

    // 1) fp16 pre-conversion + bucket-counter zeroing
    convert_kernel<<<(NXF4 + 2 * NWF4 + 255) / 256, 256>>>(x, Wp, Ws);

    // 2) both GEMMs + bucket plane in one launch
    dim3 grid(D_PROJ / 128, B_ / 128, 3);   // (8, 32, 3)
    hgemm2<<<grid, 128, SMEM_GEMM>>>(y, bp, bs, out);

    // 3) fused parent-logits + child-experts tail
    tail_kernel<<<PLOG_BLOCKS + CHILD_BLOCKS, 256>>>(Wc, bc, cw0, cb0, cw1, cb1, out);
}